// round 1
// baseline (speedup 1.0000x reference)
#include <cuda_runtime.h>
#include <cuda_bf16.h>

// Problem constants
#define NB   16          // batch
#define LSEQ 2048        // sequence length (q and kv)
#define QD   1024        // query input dim
#define KD   768         // key/value input dim
#define OD   1024        // projected dim (OUT_DIM)

// Scratch (device globals — no runtime allocation allowed)
__device__ float g_q[(size_t)NB * LSEQ * OD];           // 134 MB
__device__ float g_k[(size_t)NB * LSEQ * OD];           // 134 MB
__device__ float g_v[(size_t)NB * LSEQ * OD];           // 134 MB
__device__ float g_s[(size_t)NB * LSEQ * LSEQ];         // 268 MB (scores/probs)

// ---------------------------------------------------------------------------
// Tiled fp32 GEMM: C[M,N] = scale * (A @ B(^T)) + bias
//   A: [M,K] row-major (per-batch stride sA)
//   B: if BT: [N,K] row-major (C[m,n] = sum_k A[m,k]*B[n,k])
//      else : [K,N] row-major
//   Block tile 128x128x16, 256 threads, 8x8 per thread (split 4+4 halves).
// All dims here are multiples of the tile sizes (no bounds checks).
// ---------------------------------------------------------------------------
template<bool BT, bool BIAS>
__global__ __launch_bounds__(256)
void gemm128(const float* __restrict__ A, const float* __restrict__ B,
             const float* __restrict__ bias, float* __restrict__ C,
             int M, int N, int K,
             long long sA, long long sB, long long sC, float scale)
{
    __shared__ float As[16][128];
    __shared__ float Bs[16][128];

    const int tid = threadIdx.x;
    const int tx  = tid & 15;
    const int ty  = tid >> 4;
    const int m0  = blockIdx.y * 128;
    const int n0  = blockIdx.x * 128;

    const float* Ap = A + (long long)blockIdx.z * sA;
    const float* Bp = B + (long long)blockIdx.z * sB;

    float acc[8][8];
    #pragma unroll
    for (int i = 0; i < 8; i++)
        #pragma unroll
        for (int j = 0; j < 8; j++) acc[i][j] = 0.f;

    for (int k0 = 0; k0 < K; k0 += 16) {
        // Load A tile: 128 rows x 16 cols (512 float4, 2 per thread)
        #pragma unroll
        for (int j = 0; j < 2; j++) {
            int q = tid + j * 256;
            int r = q >> 2;
            int c = (q & 3) << 2;
            float4 v = *(const float4*)(Ap + (long long)(m0 + r) * K + k0 + c);
            As[c + 0][r] = v.x; As[c + 1][r] = v.y;
            As[c + 2][r] = v.z; As[c + 3][r] = v.w;
        }
        if (BT) {
            // B tile: 128 rows (n) x 16 cols (k) — same pattern as A
            #pragma unroll
            for (int j = 0; j < 2; j++) {
                int q = tid + j * 256;
                int r = q >> 2;
                int c = (q & 3) << 2;
                float4 v = *(const float4*)(Bp + (long long)(n0 + r) * K + k0 + c);
                Bs[c + 0][r] = v.x; Bs[c + 1][r] = v.y;
                Bs[c + 2][r] = v.z; Bs[c + 3][r] = v.w;
            }
        } else {
            // B tile: 16 rows (k) x 128 cols (n) — contiguous float4 stores
            #pragma unroll
            for (int j = 0; j < 2; j++) {
                int q = tid + j * 256;
                int r = q >> 5;
                int c = (q & 31) << 2;
                *(float4*)&Bs[r][c] =
                    *(const float4*)(Bp + (long long)(k0 + r) * N + n0 + c);
            }
        }
        __syncthreads();

        #pragma unroll
        for (int kk = 0; kk < 16; kk++) {
            float4 a0 = *(const float4*)&As[kk][ty * 4];
            float4 a1 = *(const float4*)&As[kk][ty * 4 + 64];
            float4 b0 = *(const float4*)&Bs[kk][tx * 4];
            float4 b1 = *(const float4*)&Bs[kk][tx * 4 + 64];
            float av[8] = {a0.x, a0.y, a0.z, a0.w, a1.x, a1.y, a1.z, a1.w};
            float bv[8] = {b0.x, b0.y, b0.z, b0.w, b1.x, b1.y, b1.z, b1.w};
            #pragma unroll
            for (int i = 0; i < 8; i++)
                #pragma unroll
                for (int j = 0; j < 8; j++)
                    acc[i][j] += av[i] * bv[j];
        }
        __syncthreads();
    }

    float* Cp = C + (long long)blockIdx.z * sC;
    #pragma unroll
    for (int i = 0; i < 8; i++) {
        int m = m0 + ((i < 4) ? (ty * 4 + i) : (64 + ty * 4 + (i - 4)));
        #pragma unroll
        for (int jh = 0; jh < 2; jh++) {
            int n = n0 + jh * 64 + tx * 4;
            float4 o;
            o.x = acc[i][jh * 4 + 0] * scale;
            o.y = acc[i][jh * 4 + 1] * scale;
            o.z = acc[i][jh * 4 + 2] * scale;
            o.w = acc[i][jh * 4 + 3] * scale;
            if (BIAS) {
                o.x += bias[n + 0]; o.y += bias[n + 1];
                o.z += bias[n + 2]; o.w += bias[n + 3];
            }
            *(float4*)(Cp + (long long)m * N + n) = o;
        }
    }
}

// ---------------------------------------------------------------------------
// Row softmax over rows of length LSEQ (2048), in place.
// One block (256 threads) per row; 8 elements per thread.
// ---------------------------------------------------------------------------
__global__ __launch_bounds__(256)
void softmax_rows(float* __restrict__ S)
{
    float* row = S + (long long)blockIdx.x * LSEQ;
    const int tid  = threadIdx.x;
    const int lane = tid & 31;
    const int warp = tid >> 5;

    int base = tid * 8;
    float4 x0 = *(const float4*)(row + base);
    float4 x1 = *(const float4*)(row + base + 4);
    float v[8] = {x0.x, x0.y, x0.z, x0.w, x1.x, x1.y, x1.z, x1.w};

    __shared__ float red[8];

    // --- max ---
    float mx = v[0];
    #pragma unroll
    for (int i = 1; i < 8; i++) mx = fmaxf(mx, v[i]);
    #pragma unroll
    for (int o = 16; o > 0; o >>= 1) mx = fmaxf(mx, __shfl_xor_sync(~0u, mx, o));
    if (lane == 0) red[warp] = mx;
    __syncthreads();
    float m = red[0];
    #pragma unroll
    for (int i = 1; i < 8; i++) m = fmaxf(m, red[i]);
    __syncthreads();

    // --- exp + sum ---
    float s = 0.f;
    #pragma unroll
    for (int i = 0; i < 8; i++) {
        v[i] = __expf(v[i] - m);
        s += v[i];
    }
    #pragma unroll
    for (int o = 16; o > 0; o >>= 1) s += __shfl_xor_sync(~0u, s, o);
    if (lane == 0) red[warp] = s;
    __syncthreads();
    float tot = 0.f;
    #pragma unroll
    for (int i = 0; i < 8; i++) tot += red[i];
    float inv = 1.0f / tot;

    float4 y0, y1;
    y0.x = v[0] * inv; y0.y = v[1] * inv; y0.z = v[2] * inv; y0.w = v[3] * inv;
    y1.x = v[4] * inv; y1.y = v[5] * inv; y1.z = v[6] * inv; y1.w = v[7] * inv;
    *(float4*)(row + base)     = y0;
    *(float4*)(row + base + 4) = y1;
}

// ---------------------------------------------------------------------------
// kernel_launch: 3 projection GEMMs -> scores GEMM -> softmax -> output GEMM
// ---------------------------------------------------------------------------
extern "C" void kernel_launch(void* const* d_in, const int* in_sizes, int n_in,
                              void* d_out, int out_size)
{
    const float* query = (const float*)d_in[0];
    const float* key   = (const float*)d_in[1];
    const float* value = (const float*)d_in[2];
    const float* Wq    = (const float*)d_in[3];
    const float* bq    = (const float*)d_in[4];
    const float* Wk    = (const float*)d_in[5];
    const float* bk    = (const float*)d_in[6];
    const float* Wv    = (const float*)d_in[7];
    const float* bv    = (const float*)d_in[8];
    float*       out   = (float*)d_out;

    float *gq, *gk, *gv, *gs;
    cudaGetSymbolAddress((void**)&gq, g_q);
    cudaGetSymbolAddress((void**)&gk, g_k);
    cudaGetSymbolAddress((void**)&gv, g_v);
    cudaGetSymbolAddress((void**)&gs, g_s);

    const int M = NB * LSEQ;  // 32768

    // q = query @ Wq^T + bq   [32768,1024] x [1024,1024]^T
    gemm128<true, true><<<dim3(OD / 128, M / 128, 1), 256>>>(
        query, Wq, bq, gq, M, OD, QD, 0, 0, 0, 1.0f);
    // k = key @ Wk^T + bk     [32768,768] x [1024,768]^T
    gemm128<true, true><<<dim3(OD / 128, M / 128, 1), 256>>>(
        key, Wk, bk, gk, M, OD, KD, 0, 0, 0, 1.0f);
    // v = value @ Wv^T + bv
    gemm128<true, true><<<dim3(OD / 128, M / 128, 1), 256>>>(
        value, Wv, bv, gv, M, OD, KD, 0, 0, 0, 1.0f);

    // scores = (q @ k^T) * OD^-0.5, per batch   [2048,1024] x [2048,1024]^T
    gemm128<true, false><<<dim3(LSEQ / 128, LSEQ / 128, NB), 256>>>(
        gq, gk, nullptr, gs, LSEQ, LSEQ, OD,
        (long long)LSEQ * OD, (long long)LSEQ * OD, (long long)LSEQ * LSEQ,
        0.03125f /* 1024^-0.5 = 1/32 */);

    // softmax over last dim, in place
    softmax_rows<<<NB * LSEQ, 256>>>(gs);

    // out = probs @ v, per batch   [2048,2048] x [2048,1024]
    gemm128<false, false><<<dim3(OD / 128, LSEQ / 128, NB), 256>>>(
        gs, gv, nullptr, out, LSEQ, OD, LSEQ,
        (long long)LSEQ * LSEQ, (long long)LSEQ * OD, (long long)LSEQ * OD,
        1.0f);
}

// round 2
// speedup vs baseline: 1.0006x; 1.0006x over previous
#include <cuda_runtime.h>
#include <cuda_bf16.h>

// Problem constants
#define NB   16          // batch
#define LSEQ 2048        // sequence length (q and kv)
#define QD   1024        // query input dim
#define KD   768         // key/value input dim
#define OD   1024        // projected dim (OUT_DIM)

// Scratch (device globals — no runtime allocation allowed)
__device__ float g_q[(size_t)NB * LSEQ * OD];           // 134 MB
__device__ float g_k[(size_t)NB * LSEQ * OD];           // 134 MB
__device__ float g_v[(size_t)NB * LSEQ * OD];           // 134 MB
__device__ float g_s[(size_t)NB * LSEQ * LSEQ];         // 268 MB (scores/probs)

// ---------------------------------------------------------------------------
// Tiled fp32 GEMM: C[M,N] = scale * (A @ B(^T)) + bias
//   A: [M,K] row-major (per-batch stride sA)
//   B: if BT: [N,K] row-major (C[m,n] = sum_k A[m,k]*B[n,k])
//      else : [K,N] row-major
//   Block tile 128x128x16, 256 threads, 8x8 per thread (split 4+4 halves).
// All dims here are multiples of the tile sizes (no bounds checks).
// ---------------------------------------------------------------------------
template<bool BT, bool BIAS>
__global__ __launch_bounds__(256)
void gemm128(const float* __restrict__ A, const float* __restrict__ B,
             const float* __restrict__ bias, float* __restrict__ C,
             int M, int N, int K,
             long long sA, long long sB, long long sC, float scale)
{
    __shared__ float As[16][128];
    __shared__ float Bs[16][128];

    const int tid = threadIdx.x;
    const int tx  = tid & 15;
    const int ty  = tid >> 4;
    const int m0  = blockIdx.y * 128;
    const int n0  = blockIdx.x * 128;

    const float* Ap = A + (long long)blockIdx.z * sA;
    const float* Bp = B + (long long)blockIdx.z * sB;

    float acc[8][8];
    #pragma unroll
    for (int i = 0; i < 8; i++)
        #pragma unroll
        for (int j = 0; j < 8; j++) acc[i][j] = 0.f;

    for (int k0 = 0; k0 < K; k0 += 16) {
        // Load A tile: 128 rows x 16 cols (512 float4, 2 per thread)
        #pragma unroll
        for (int j = 0; j < 2; j++) {
            int q = tid + j * 256;
            int r = q >> 2;
            int c = (q & 3) << 2;
            float4 v = *(const float4*)(Ap + (long long)(m0 + r) * K + k0 + c);
            As[c + 0][r] = v.x; As[c + 1][r] = v.y;
            As[c + 2][r] = v.z; As[c + 3][r] = v.w;
        }
        if (BT) {
            // B tile: 128 rows (n) x 16 cols (k) — same pattern as A
            #pragma unroll
            for (int j = 0; j < 2; j++) {
                int q = tid + j * 256;
                int r = q >> 2;
                int c = (q & 3) << 2;
                float4 v = *(const float4*)(Bp + (long long)(n0 + r) * K + k0 + c);
                Bs[c + 0][r] = v.x; Bs[c + 1][r] = v.y;
                Bs[c + 2][r] = v.z; Bs[c + 3][r] = v.w;
            }
        } else {
            // B tile: 16 rows (k) x 128 cols (n) — contiguous float4 stores
            #pragma unroll
            for (int j = 0; j < 2; j++) {
                int q = tid + j * 256;
                int r = q >> 5;
                int c = (q & 31) << 2;
                *(float4*)&Bs[r][c] =
                    *(const float4*)(Bp + (long long)(k0 + r) * N + n0 + c);
            }
        }
        __syncthreads();

        #pragma unroll
        for (int kk = 0; kk < 16; kk++) {
            float4 a0 = *(const float4*)&As[kk][ty * 4];
            float4 a1 = *(const float4*)&As[kk][ty * 4 + 64];
            float4 b0 = *(const float4*)&Bs[kk][tx * 4];
            float4 b1 = *(const float4*)&Bs[kk][tx * 4 + 64];
            float av[8] = {a0.x, a0.y, a0.z, a0.w, a1.x, a1.y, a1.z, a1.w};
            float bv[8] = {b0.x, b0.y, b0.z, b0.w, b1.x, b1.y, b1.z, b1.w};
            #pragma unroll
            for (int i = 0; i < 8; i++)
                #pragma unroll
                for (int j = 0; j < 8; j++)
                    acc[i][j] += av[i] * bv[j];
        }
        __syncthreads();
    }

    float* Cp = C + (long long)blockIdx.z * sC;
    #pragma unroll
    for (int i = 0; i < 8; i++) {
        int m = m0 + ((i < 4) ? (ty * 4 + i) : (64 + ty * 4 + (i - 4)));
        #pragma unroll
        for (int jh = 0; jh < 2; jh++) {
            int n = n0 + jh * 64 + tx * 4;
            float4 o;
            o.x = acc[i][jh * 4 + 0] * scale;
            o.y = acc[i][jh * 4 + 1] * scale;
            o.z = acc[i][jh * 4 + 2] * scale;
            o.w = acc[i][jh * 4 + 3] * scale;
            if (BIAS) {
                o.x += bias[n + 0]; o.y += bias[n + 1];
                o.z += bias[n + 2]; o.w += bias[n + 3];
            }
            *(float4*)(Cp + (long long)m * N + n) = o;
        }
    }
}

// ---------------------------------------------------------------------------
// Row softmax over rows of length LSEQ (2048), in place.
// One block (256 threads) per row; 8 elements per thread.
// ---------------------------------------------------------------------------
__global__ __launch_bounds__(256)
void softmax_rows(float* __restrict__ S)
{
    float* row = S + (long long)blockIdx.x * LSEQ;
    const int tid  = threadIdx.x;
    const int lane = tid & 31;
    const int warp = tid >> 5;

    int base = tid * 8;
    float4 x0 = *(const float4*)(row + base);
    float4 x1 = *(const float4*)(row + base + 4);
    float v[8] = {x0.x, x0.y, x0.z, x0.w, x1.x, x1.y, x1.z, x1.w};

    __shared__ float red[8];

    // --- max ---
    float mx = v[0];
    #pragma unroll
    for (int i = 1; i < 8; i++) mx = fmaxf(mx, v[i]);
    #pragma unroll
    for (int o = 16; o > 0; o >>= 1) mx = fmaxf(mx, __shfl_xor_sync(~0u, mx, o));
    if (lane == 0) red[warp] = mx;
    __syncthreads();
    float m = red[0];
    #pragma unroll
    for (int i = 1; i < 8; i++) m = fmaxf(m, red[i]);
    __syncthreads();

    // --- exp + sum ---
    float s = 0.f;
    #pragma unroll
    for (int i = 0; i < 8; i++) {
        v[i] = __expf(v[i] - m);
        s += v[i];
    }
    #pragma unroll
    for (int o = 16; o > 0; o >>= 1) s += __shfl_xor_sync(~0u, s, o);
    if (lane == 0) red[warp] = s;
    __syncthreads();
    float tot = 0.f;
    #pragma unroll
    for (int i = 0; i < 8; i++) tot += red[i];
    float inv = 1.0f / tot;

    float4 y0, y1;
    y0.x = v[0] * inv; y0.y = v[1] * inv; y0.z = v[2] * inv; y0.w = v[3] * inv;
    y1.x = v[4] * inv; y1.y = v[5] * inv; y1.z = v[6] * inv; y1.w = v[7] * inv;
    *(float4*)(row + base)     = y0;
    *(float4*)(row + base + 4) = y1;
}

// ---------------------------------------------------------------------------
// kernel_launch: 3 projection GEMMs -> scores GEMM -> softmax -> output GEMM
// ---------------------------------------------------------------------------
extern "C" void kernel_launch(void* const* d_in, const int* in_sizes, int n_in,
                              void* d_out, int out_size)
{
    const float* query = (const float*)d_in[0];
    const float* key   = (const float*)d_in[1];
    const float* value = (const float*)d_in[2];
    const float* Wq    = (const float*)d_in[3];
    const float* bq    = (const float*)d_in[4];
    const float* Wk    = (const float*)d_in[5];
    const float* bk    = (const float*)d_in[6];
    const float* Wv    = (const float*)d_in[7];
    const float* bv    = (const float*)d_in[8];
    float*       out   = (float*)d_out;

    float *gq, *gk, *gv, *gs;
    cudaGetSymbolAddress((void**)&gq, g_q);
    cudaGetSymbolAddress((void**)&gk, g_k);
    cudaGetSymbolAddress((void**)&gv, g_v);
    cudaGetSymbolAddress((void**)&gs, g_s);

    const int M = NB * LSEQ;  // 32768

    // q = query @ Wq^T + bq   [32768,1024] x [1024,1024]^T
    gemm128<true, true><<<dim3(OD / 128, M / 128, 1), 256>>>(
        query, Wq, bq, gq, M, OD, QD, 0, 0, 0, 1.0f);
    // k = key @ Wk^T + bk     [32768,768] x [1024,768]^T
    gemm128<true, true><<<dim3(OD / 128, M / 128, 1), 256>>>(
        key, Wk, bk, gk, M, OD, KD, 0, 0, 0, 1.0f);
    // v = value @ Wv^T + bv
    gemm128<true, true><<<dim3(OD / 128, M / 128, 1), 256>>>(
        value, Wv, bv, gv, M, OD, KD, 0, 0, 0, 1.0f);

    // scores = (q @ k^T) * OD^-0.5, per batch   [2048,1024] x [2048,1024]^T
    gemm128<true, false><<<dim3(LSEQ / 128, LSEQ / 128, NB), 256>>>(
        gq, gk, nullptr, gs, LSEQ, LSEQ, OD,
        (long long)LSEQ * OD, (long long)LSEQ * OD, (long long)LSEQ * LSEQ,
        0.03125f /* 1024^-0.5 = 1/32 */);

    // softmax over last dim, in place
    softmax_rows<<<NB * LSEQ, 256>>>(gs);

    // out = probs @ v, per batch   [2048,2048] x [2048,1024]
    gemm128<false, false><<<dim3(OD / 128, LSEQ / 128, NB), 256>>>(
        gs, gv, nullptr, out, LSEQ, OD, LSEQ,
        (long long)LSEQ * LSEQ, (long long)LSEQ * OD, (long long)LSEQ * OD,
        1.0f);
}

// round 4
// speedup vs baseline: 2.3643x; 2.3628x over previous
#include <cuda_runtime.h>
#include <cuda_bf16.h>
#include <cstdint>
#include <cstddef>

#define NB   16
#define LSEQ 2048
#define QD   1024
#define KD   768
#define OD   1024
#define KPQ  (3*QD)    // 3072
#define KPK  (3*KD)    // 2304
#define KPS  (3*LSEQ)  // 6144

// ---------------- scratch (device globals) ----------------
__device__ __align__(1024) __nv_bfloat16 g_Aq[(size_t)NB*LSEQ*KPQ];
__device__ __align__(1024) __nv_bfloat16 g_Ak[(size_t)NB*LSEQ*KPK];
__device__ __align__(1024) __nv_bfloat16 g_Av[(size_t)NB*LSEQ*KPK];
__device__ __align__(1024) __nv_bfloat16 g_Bq[(size_t)OD*KPQ];
__device__ __align__(1024) __nv_bfloat16 g_Bk[(size_t)OD*KPK];
__device__ __align__(1024) __nv_bfloat16 g_Bv[(size_t)OD*KPK];
__device__ __align__(1024) float         g_q [(size_t)NB*LSEQ*OD];
__device__ __align__(1024) float         g_k [(size_t)NB*LSEQ*OD];
__device__ __align__(1024) float         g_v [(size_t)NB*LSEQ*OD];
__device__ __align__(1024) __nv_bfloat16 g_qA[(size_t)NB*LSEQ*(3*OD)];
__device__ __align__(1024) __nv_bfloat16 g_kB[(size_t)NB*LSEQ*(3*OD)];
__device__ __align__(1024) __nv_bfloat16 g_vT[(size_t)NB*OD*KPS];
__device__ __align__(1024) float         g_s [(size_t)NB*LSEQ*LSEQ];
__device__ __align__(1024) __nv_bfloat16 g_p [(size_t)NB*LSEQ*KPS];

// ---------------- helpers ----------------
__device__ __forceinline__ uint32_t smem_u32(const void* p) {
    uint32_t a;
    asm("{ .reg .u64 t; cvta.to.shared.u64 t, %1; cvt.u32.u64 %0, t; }" : "=r"(a) : "l"(p));
    return a;
}
#define SWZ(x) ((x) ^ (((x) >> 3) & 0x70))

__device__ __forceinline__ void cp16(uint32_t s, const void* g) {
    asm volatile("cp.async.cg.shared.global [%0], [%1], 16;" :: "r"(s), "l"(g));
}
__device__ __forceinline__ void cp_commit() { asm volatile("cp.async.commit_group;" ::: "memory"); }
template<int N> __device__ __forceinline__ void cp_wait() {
    asm volatile("cp.async.wait_group %0;" :: "n"(N) : "memory");
}
#define LDSM_X4(r0, r1, r2, r3, addr) \
    asm volatile("ldmatrix.sync.aligned.m8n8.x4.shared.b16 {%0,%1,%2,%3}, [%4];" \
        : "=r"(r0), "=r"(r1), "=r"(r2), "=r"(r3) : "r"(addr))
#define MMA_BF16(d, a, b) \
    asm volatile("mma.sync.aligned.m16n8k16.row.col.f32.bf16.bf16.f32 " \
        "{%0,%1,%2,%3}, {%4,%5,%6,%7}, {%8,%9}, {%0,%1,%2,%3};" \
        : "+f"((d)[0]), "+f"((d)[1]), "+f"((d)[2]), "+f"((d)[3]) \
        : "r"((a)[0]), "r"((a)[1]), "r"((a)[2]), "r"((a)[3]), "r"((b)[0]), "r"((b)[1]))

__device__ __forceinline__ void split2(float v, __nv_bfloat16& hi, __nv_bfloat16& lo) {
    hi = __float2bfloat16(v);
    lo = __float2bfloat16(v - __bfloat162float(hi));
}

// ---------------------------------------------------------------------------
// HMMA GEMM: C[M,N] = scale*(A @ B^T) (+bias).  A:[M,K] bf16 K-major,
// B:[N,K] bf16 K-major, C fp32 (ld=ldo). Tile 128x128x64, 256 threads,
// 3-stage cp.async pipeline, ldmatrix + mma.sync m16n8k16.  K % 64 == 0, K/64 >= 3.
// ---------------------------------------------------------------------------
#define GSMEM (1024 + 3*32768)
template<bool BIAS>
__global__ __launch_bounds__(256)
void mma_gemm(const __nv_bfloat16* __restrict__ A, const __nv_bfloat16* __restrict__ B,
              float* __restrict__ C, const float* __restrict__ bias,
              int K, size_t sA, size_t sB, size_t sC, int ldo, float scale)
{
    extern __shared__ char dsm[];
    const uint32_t raw  = smem_u32(dsm);
    const uint32_t STG  = (raw + 1023u) & ~1023u;

    const int tid  = threadIdx.x;
    const int wid  = tid >> 5;
    const int lane = tid & 31;
    const int wm   = wid & 3;        // 4 warps along M
    const int wn   = wid >> 2;       // 2 warps along N
    const int rowt = tid >> 3;       // 0..31
    const int segt = tid & 7;

    const __nv_bfloat16* Ab = A + blockIdx.z * sA + (size_t)(blockIdx.y * 128) * K;
    const __nv_bfloat16* Bb = B + blockIdx.z * sB + (size_t)(blockIdx.x * 128) * K;
    const int nk = K >> 6;

    auto loadChunk = [&](int c, int slot) {
        const uint32_t sb = STG + (uint32_t)slot * 32768u;
        const __nv_bfloat16* ag = Ab + (size_t)rowt * K + (size_t)c * 64 + segt * 8;
        const __nv_bfloat16* bg = Bb + (size_t)rowt * K + (size_t)c * 64 + segt * 8;
        #pragma unroll
        for (int j = 0; j < 4; j++) {
            uint32_t off = SWZ((uint32_t)((rowt + j * 32) * 128 + segt * 16));
            cp16(sb + off, ag + (size_t)j * 32 * K);
            cp16(sb + 16384u + off, bg + (size_t)j * 32 * K);
        }
    };
    loadChunk(0, 0); cp_commit();
    loadChunk(1, 1); cp_commit();
    loadChunk(2, 2); cp_commit();

    float acc[2][8][4];
    #pragma unroll
    for (int mf = 0; mf < 2; mf++)
        #pragma unroll
        for (int nf = 0; nf < 8; nf++)
            #pragma unroll
            for (int e = 0; e < 4; e++) acc[mf][nf][e] = 0.f;

    // ldmatrix address components (per thread, within tile)
    const int aRow = wm * 32 + (lane & 7) + ((lane >> 3) & 1) * 8;   // + mf*16
    const int aCol = ((lane >> 4) & 1) * 16;                          // + kk*32
    const int bRow = wn * 64 + (lane & 7) + ((lane >> 4) & 1) * 8;   // + p*16
    const int bCol = ((lane >> 3) & 1) * 16;                          // + kk*32

    for (int i = 0; i < nk; ++i) {
        const int slot = i % 3;
        cp_wait<2>();
        __syncthreads();
        const uint32_t aB = STG + (uint32_t)slot * 32768u;
        const uint32_t bB = aB + 16384u;
        #pragma unroll
        for (int kk = 0; kk < 4; kk++) {
            uint32_t a[2][4], b[8][2];
            #pragma unroll
            for (int mf = 0; mf < 2; mf++) {
                uint32_t ad = aB + SWZ((uint32_t)((aRow + mf * 16) * 128 + aCol + kk * 32));
                LDSM_X4(a[mf][0], a[mf][1], a[mf][2], a[mf][3], ad);
            }
            #pragma unroll
            for (int p = 0; p < 4; p++) {
                uint32_t bd = bB + SWZ((uint32_t)((bRow + p * 16) * 128 + bCol + kk * 32));
                LDSM_X4(b[2*p][0], b[2*p][1], b[2*p+1][0], b[2*p+1][1], bd);
            }
            #pragma unroll
            for (int mf = 0; mf < 2; mf++)
                #pragma unroll
                for (int nf = 0; nf < 8; nf++)
                    MMA_BF16(acc[mf][nf], a[mf], b[nf]);
        }
        __syncthreads();
        if (i + 3 < nk) loadChunk(i + 3, slot);
        cp_commit();
    }

    // epilogue
    const int gid = lane >> 2, q4 = lane & 3;
    const int m0 = blockIdx.y * 128 + wm * 32;
    const int n0 = blockIdx.x * 128 + wn * 64;
    float* Cb = C + blockIdx.z * sC;
    #pragma unroll
    for (int mf = 0; mf < 2; mf++) {
        #pragma unroll
        for (int nf = 0; nf < 8; nf++) {
            const int n = n0 + nf * 8 + q4 * 2;
            float bx = 0.f, by = 0.f;
            if (BIAS) { bx = __ldg(bias + n); by = __ldg(bias + n + 1); }
            const int mA = m0 + mf * 16 + gid;
            float2 v0 = { acc[mf][nf][0] * scale + bx, acc[mf][nf][1] * scale + by };
            float2 v1 = { acc[mf][nf][2] * scale + bx, acc[mf][nf][3] * scale + by };
            *(float2*)(Cb + (size_t)mA * ldo + n)        = v0;
            *(float2*)(Cb + (size_t)(mA + 8) * ldo + n)  = v1;
        }
    }
}

// ---------------------------------------------------------------------------
// split-pack: in [R,D] fp32 -> out [R,3D] bf16.  APACK: [hi|lo|hi], else [hi|hi|lo]
// ---------------------------------------------------------------------------
template<bool APACK>
__global__ __launch_bounds__(256)
void pack_split(const float* __restrict__ in, __nv_bfloat16* __restrict__ out,
                int D, size_t total4)
{
    size_t i = (size_t)blockIdx.x * 256 + threadIdx.x;
    if (i >= total4) return;
    const int d4 = D >> 2;
    size_t r = i / d4;
    int c = (int)(i % d4) * 4;
    float4 x = *(const float4*)(in + r * D + c);
    __nv_bfloat16 h[4], l[4];
    split2(x.x, h[0], l[0]); split2(x.y, h[1], l[1]);
    split2(x.z, h[2], l[2]); split2(x.w, h[3], l[3]);
    __nv_bfloat16* o = out + r * (size_t)(3 * D) + c;
    *(__nv_bfloat162*)(o + 0) = {h[0], h[1]};
    *(__nv_bfloat162*)(o + 2) = {h[2], h[3]};
    __nv_bfloat16* o1 = o + D, * o2 = o + 2 * D;
    if (APACK) {
        *(__nv_bfloat162*)(o1 + 0) = {l[0], l[1]}; *(__nv_bfloat162*)(o1 + 2) = {l[2], l[3]};
        *(__nv_bfloat162*)(o2 + 0) = {h[0], h[1]}; *(__nv_bfloat162*)(o2 + 2) = {h[2], h[3]};
    } else {
        *(__nv_bfloat162*)(o1 + 0) = {h[0], h[1]}; *(__nv_bfloat162*)(o1 + 2) = {h[2], h[3]};
        *(__nv_bfloat162*)(o2 + 0) = {l[0], l[1]}; *(__nv_bfloat162*)(o2 + 2) = {l[2], l[3]};
    }
}

// ---------------------------------------------------------------------------
// transpose-pack: v [b, LSEQ, OD] fp32 -> vT [b, OD, 3*LSEQ] bf16 [hi|hi|lo]
// ---------------------------------------------------------------------------
__global__ __launch_bounds__(256)
void transpose_pack(const float* __restrict__ v, __nv_bfloat16* __restrict__ vt)
{
    __shared__ float t[32][33];
    const int b = blockIdx.z;
    const int o0 = blockIdx.x * 32, s0 = blockIdx.y * 32;
    const int tx = threadIdx.x & 31, ty = threadIdx.x >> 5;
    #pragma unroll
    for (int j = 0; j < 4; j++)
        t[ty + j * 8][tx] = v[((size_t)b * LSEQ + s0 + ty + j * 8) * OD + o0 + tx];
    __syncthreads();
    #pragma unroll
    for (int j = 0; j < 4; j++) {
        const int o = o0 + ty + j * 8, s = s0 + tx;
        float x = t[tx][ty + j * 8];
        __nv_bfloat16 hi, lo; split2(x, hi, lo);
        __nv_bfloat16* dst = vt + ((size_t)b * OD + o) * KPS + s;
        dst[0] = hi; dst[LSEQ] = hi; dst[2 * LSEQ] = lo;
    }
}

// ---------------------------------------------------------------------------
// softmax over rows (len 2048) -> packed probs [hi|lo|hi] rows of 6144
// ---------------------------------------------------------------------------
__global__ __launch_bounds__(256)
void softmax_pack(const float* __restrict__ S, __nv_bfloat16* __restrict__ P)
{
    const float* row = S + (size_t)blockIdx.x * LSEQ;
    __nv_bfloat16* prow = P + (size_t)blockIdx.x * KPS;
    const int tid = threadIdx.x, lane = tid & 31, warp = tid >> 5;
    const int b0 = tid * 8;
    float4 x0 = *(const float4*)(row + b0);
    float4 x1 = *(const float4*)(row + b0 + 4);
    float v[8] = {x0.x, x0.y, x0.z, x0.w, x1.x, x1.y, x1.z, x1.w};
    __shared__ float red[8];
    float mx = v[0];
    #pragma unroll
    for (int i = 1; i < 8; i++) mx = fmaxf(mx, v[i]);
    #pragma unroll
    for (int o = 16; o > 0; o >>= 1) mx = fmaxf(mx, __shfl_xor_sync(~0u, mx, o));
    if (lane == 0) red[warp] = mx;
    __syncthreads();
    float m = red[0];
    #pragma unroll
    for (int i = 1; i < 8; i++) m = fmaxf(m, red[i]);
    __syncthreads();
    float s = 0.f;
    #pragma unroll
    for (int i = 0; i < 8; i++) { v[i] = __expf(v[i] - m); s += v[i]; }
    #pragma unroll
    for (int o = 16; o > 0; o >>= 1) s += __shfl_xor_sync(~0u, s, o);
    if (lane == 0) red[warp] = s;
    __syncthreads();
    float tot = 0.f;
    #pragma unroll
    for (int i = 0; i < 8; i++) tot += red[i];
    float inv = 1.0f / tot;
    #pragma unroll
    for (int i = 0; i < 8; i += 2) {
        __nv_bfloat16 h0, l0, h1, l1;
        split2(v[i] * inv, h0, l0);
        split2(v[i + 1] * inv, h1, l1);
        *(__nv_bfloat162*)(prow + b0 + i)            = {h0, h1};
        *(__nv_bfloat162*)(prow + LSEQ + b0 + i)     = {l0, l1};
        *(__nv_bfloat162*)(prow + 2 * LSEQ + b0 + i) = {h0, h1};
    }
}

// ---------------------------------------------------------------------------
extern "C" void kernel_launch(void* const* d_in, const int* in_sizes, int n_in,
                              void* d_out, int out_size)
{
    const float* query = (const float*)d_in[0];
    const float* key   = (const float*)d_in[1];
    const float* value = (const float*)d_in[2];
    const float* Wq    = (const float*)d_in[3];
    const float* bq    = (const float*)d_in[4];
    const float* Wk    = (const float*)d_in[5];
    const float* bk    = (const float*)d_in[6];
    const float* Wv    = (const float*)d_in[7];
    const float* bv    = (const float*)d_in[8];
    float*       out   = (float*)d_out;

    __nv_bfloat16 *aq, *ak, *av, *bqp, *bkp, *bvp, *qA, *kB, *vT, *pP;
    float *q, *k, *v, *s;
    cudaGetSymbolAddress((void**)&aq,  g_Aq);
    cudaGetSymbolAddress((void**)&ak,  g_Ak);
    cudaGetSymbolAddress((void**)&av,  g_Av);
    cudaGetSymbolAddress((void**)&bqp, g_Bq);
    cudaGetSymbolAddress((void**)&bkp, g_Bk);
    cudaGetSymbolAddress((void**)&bvp, g_Bv);
    cudaGetSymbolAddress((void**)&q,   g_q);
    cudaGetSymbolAddress((void**)&k,   g_k);
    cudaGetSymbolAddress((void**)&v,   g_v);
    cudaGetSymbolAddress((void**)&qA,  g_qA);
    cudaGetSymbolAddress((void**)&kB,  g_kB);
    cudaGetSymbolAddress((void**)&vT,  g_vT);
    cudaGetSymbolAddress((void**)&s,   g_s);
    cudaGetSymbolAddress((void**)&pP,  g_p);

    cudaFuncSetAttribute(mma_gemm<true>,  cudaFuncAttributeMaxDynamicSharedMemorySize, GSMEM);
    cudaFuncSetAttribute(mma_gemm<false>, cudaFuncAttributeMaxDynamicSharedMemorySize, GSMEM);

    const int M = NB * LSEQ;  // 32768

    // 1) split-pack inputs and weights
    pack_split<true ><<<(M * QD / 4 + 255) / 256, 256>>>(query, aq, QD, (size_t)M * QD / 4);
    pack_split<true ><<<(M * KD / 4 + 255) / 256, 256>>>(key,   ak, KD, (size_t)M * KD / 4);
    pack_split<true ><<<(M * KD / 4 + 255) / 256, 256>>>(value, av, KD, (size_t)M * KD / 4);
    pack_split<false><<<(OD * QD / 4 + 255) / 256, 256>>>(Wq, bqp, QD, (size_t)OD * QD / 4);
    pack_split<false><<<(OD * KD / 4 + 255) / 256, 256>>>(Wk, bkp, KD, (size_t)OD * KD / 4);
    pack_split<false><<<(OD * KD / 4 + 255) / 256, 256>>>(Wv, bvp, KD, (size_t)OD * KD / 4);

    // 2) projections: q/k/v fp32
    mma_gemm<true><<<dim3(OD/128, M/128, 1), 256, GSMEM>>>(aq, bqp, q, bq, KPQ, 0, 0, 0, OD, 1.f);
    mma_gemm<true><<<dim3(OD/128, M/128, 1), 256, GSMEM>>>(ak, bkp, k, bk, KPK, 0, 0, 0, OD, 1.f);
    mma_gemm<true><<<dim3(OD/128, M/128, 1), 256, GSMEM>>>(av, bvp, v, bv, KPK, 0, 0, 0, OD, 1.f);

    // 3) re-pack q (A) / k (B), transpose-pack v
    pack_split<true ><<<(M * OD / 4 + 255) / 256, 256>>>(q, qA, OD, (size_t)M * OD / 4);
    pack_split<false><<<(M * OD / 4 + 255) / 256, 256>>>(k, kB, OD, (size_t)M * OD / 4);
    transpose_pack<<<dim3(OD/32, LSEQ/32, NB), 256>>>(v, vT);

    // 4) scores = (q k^T)/32, per batch
    mma_gemm<false><<<dim3(LSEQ/128, LSEQ/128, NB), 256, GSMEM>>>(
        qA, kB, s, nullptr, 3*OD,
        (size_t)LSEQ*3*OD, (size_t)LSEQ*3*OD, (size_t)LSEQ*LSEQ, LSEQ, 0.03125f);

    // 5) softmax + pack probs
    softmax_pack<<<NB * LSEQ, 256>>>(s, pP);

    // 6) out = probs @ v, per batch
    mma_gemm<false><<<dim3(OD/128, LSEQ/128, NB), 256, GSMEM>>>(
        pP, vT, out, nullptr, KPS,
        (size_t)LSEQ*KPS, (size_t)OD*KPS, (size_t)LSEQ*OD, OD, 1.f);
}

// round 5
// speedup vs baseline: 2.3690x; 1.0020x over previous
#include <cuda_runtime.h>
#include <cuda_bf16.h>
#include <cstdint>
#include <cstddef>

#define NB   16
#define LSEQ 2048
#define QD   1024
#define KD   768
#define OD   1024
#define KPQ  (3*QD)    // 3072
#define KPK  (3*KD)    // 2304
#define KPS  (3*LSEQ)  // 6144

// ---------------- scratch (device globals) ----------------
__device__ __align__(1024) __nv_bfloat16 g_Aq[(size_t)NB*LSEQ*KPQ];
__device__ __align__(1024) __nv_bfloat16 g_Ak[(size_t)NB*LSEQ*KPK];
__device__ __align__(1024) __nv_bfloat16 g_Av[(size_t)NB*LSEQ*KPK];
__device__ __align__(1024) __nv_bfloat16 g_Bq[(size_t)OD*KPQ];
__device__ __align__(1024) __nv_bfloat16 g_Bk[(size_t)OD*KPK];
__device__ __align__(1024) __nv_bfloat16 g_Bv[(size_t)OD*KPK];
__device__ __align__(1024) __nv_bfloat16 g_qA[(size_t)NB*LSEQ*(3*OD)];
__device__ __align__(1024) __nv_bfloat16 g_kB[(size_t)NB*LSEQ*(3*OD)];
__device__ __align__(1024) __nv_bfloat16 g_vT[(size_t)NB*OD*KPS];
__device__ __align__(1024) float         g_s [(size_t)NB*LSEQ*LSEQ];
__device__ __align__(1024) __nv_bfloat16 g_p [(size_t)NB*LSEQ*KPS];

// ---------------- helpers ----------------
__device__ __forceinline__ uint32_t smem_u32(const void* p) {
    uint32_t a;
    asm("{ .reg .u64 t; cvta.to.shared.u64 t, %1; cvt.u32.u64 %0, t; }" : "=r"(a) : "l"(p));
    return a;
}
#define SWZ(x) ((x) ^ (((x) >> 3) & 0x70))

__device__ __forceinline__ void cp16(uint32_t s, const void* g) {
    asm volatile("cp.async.cg.shared.global [%0], [%1], 16;" :: "r"(s), "l"(g));
}
__device__ __forceinline__ void cp_commit() { asm volatile("cp.async.commit_group;" ::: "memory"); }
template<int N> __device__ __forceinline__ void cp_wait() {
    asm volatile("cp.async.wait_group %0;" :: "n"(N) : "memory");
}
#define LDSM_X4(r0, r1, r2, r3, addr) \
    asm volatile("ldmatrix.sync.aligned.m8n8.x4.shared.b16 {%0,%1,%2,%3}, [%4];" \
        : "=r"(r0), "=r"(r1), "=r"(r2), "=r"(r3) : "r"(addr))
#define MMA_BF16(d, a, b) \
    asm volatile("mma.sync.aligned.m16n8k16.row.col.f32.bf16.bf16.f32 " \
        "{%0,%1,%2,%3}, {%4,%5,%6,%7}, {%8,%9}, {%0,%1,%2,%3};" \
        : "+f"((d)[0]), "+f"((d)[1]), "+f"((d)[2]), "+f"((d)[3]) \
        : "r"((a)[0]), "r"((a)[1]), "r"((a)[2]), "r"((a)[3]), "r"((b)[0]), "r"((b)[1]))

__device__ __forceinline__ void split2(float v, __nv_bfloat16& hi, __nv_bfloat16& lo) {
    hi = __float2bfloat16(v);
    lo = __float2bfloat16(v - __bfloat162float(hi));
}

// epilogue variants
#define EPI_F32   0   // fp32 C, scale (+bias)
#define EPI_PACKA 1   // bf16 [hi|lo|hi] rows, +bias (seg = D)
#define EPI_PACKB 2   // bf16 [hi|hi|lo] rows, +bias (seg = D)
#define EPI_VT    3   // transposed pack into vT [b, OD, 3*LSEQ], +bias

// ---------------------------------------------------------------------------
// HMMA GEMM: A:[M,K] bf16 K-major, B:[N,K] bf16 K-major.
// Tile 128x128x64, 256 threads, 3-stage cp.async, ldmatrix + mma m16n8k16.
// K % 64 == 0, K/64 >= 3.
// ---------------------------------------------------------------------------
#define GSMEM (1024 + 3*32768)
template<int EPI>
__global__ __launch_bounds__(256)
void mma_gemm(const __nv_bfloat16* __restrict__ A, const __nv_bfloat16* __restrict__ B,
              void* __restrict__ Cv, const float* __restrict__ bias,
              int K, size_t sA, size_t sB, size_t sC, int ldo, int seg, float scale)
{
    extern __shared__ char dsm[];
    const uint32_t raw  = smem_u32(dsm);
    const uint32_t STG  = (raw + 1023u) & ~1023u;

    const int tid  = threadIdx.x;
    const int wid  = tid >> 5;
    const int lane = tid & 31;
    const int wm   = wid & 3;
    const int wn   = wid >> 2;
    const int rowt = tid >> 3;
    const int segt = tid & 7;

    const __nv_bfloat16* Ab = A + blockIdx.z * sA + (size_t)(blockIdx.y * 128) * K;
    const __nv_bfloat16* Bb = B + blockIdx.z * sB + (size_t)(blockIdx.x * 128) * K;
    const int nk = K >> 6;

    auto loadChunk = [&](int c, int slot) {
        const uint32_t sb = STG + (uint32_t)slot * 32768u;
        const __nv_bfloat16* ag = Ab + (size_t)rowt * K + (size_t)c * 64 + segt * 8;
        const __nv_bfloat16* bg = Bb + (size_t)rowt * K + (size_t)c * 64 + segt * 8;
        #pragma unroll
        for (int j = 0; j < 4; j++) {
            uint32_t off = SWZ((uint32_t)((rowt + j * 32) * 128 + segt * 16));
            cp16(sb + off, ag + (size_t)j * 32 * K);
            cp16(sb + 16384u + off, bg + (size_t)j * 32 * K);
        }
    };
    loadChunk(0, 0); cp_commit();
    loadChunk(1, 1); cp_commit();
    loadChunk(2, 2); cp_commit();

    float acc[2][8][4];
    #pragma unroll
    for (int mf = 0; mf < 2; mf++)
        #pragma unroll
        for (int nf = 0; nf < 8; nf++)
            #pragma unroll
            for (int e = 0; e < 4; e++) acc[mf][nf][e] = 0.f;

    const int aRow = wm * 32 + (lane & 7) + ((lane >> 3) & 1) * 8;
    const int aCol = ((lane >> 4) & 1) * 16;
    const int bRow = wn * 64 + (lane & 7) + ((lane >> 4) & 1) * 8;
    const int bCol = ((lane >> 3) & 1) * 16;

    for (int i = 0; i < nk; ++i) {
        const int slot = i % 3;
        cp_wait<2>();
        __syncthreads();
        const uint32_t aB = STG + (uint32_t)slot * 32768u;
        const uint32_t bB = aB + 16384u;
        #pragma unroll
        for (int kk = 0; kk < 4; kk++) {
            uint32_t a[2][4], b[8][2];
            #pragma unroll
            for (int mf = 0; mf < 2; mf++) {
                uint32_t ad = aB + SWZ((uint32_t)((aRow + mf * 16) * 128 + aCol + kk * 32));
                LDSM_X4(a[mf][0], a[mf][1], a[mf][2], a[mf][3], ad);
            }
            #pragma unroll
            for (int p = 0; p < 4; p++) {
                uint32_t bd = bB + SWZ((uint32_t)((bRow + p * 16) * 128 + bCol + kk * 32));
                LDSM_X4(b[2*p][0], b[2*p][1], b[2*p+1][0], b[2*p+1][1], bd);
            }
            #pragma unroll
            for (int mf = 0; mf < 2; mf++)
                #pragma unroll
                for (int nf = 0; nf < 8; nf++)
                    MMA_BF16(acc[mf][nf], a[mf], b[nf]);
        }
        __syncthreads();
        if (i + 3 < nk) loadChunk(i + 3, slot);
        cp_commit();
    }

    // ------------------------- epilogues -------------------------
    const int gid = lane >> 2, q4 = lane & 3;
    const int m0 = blockIdx.y * 128 + wm * 32;
    const int n0 = blockIdx.x * 128 + wn * 64;

    if (EPI == EPI_F32) {
        float* Cb = (float*)Cv + blockIdx.z * sC;
        #pragma unroll
        for (int mf = 0; mf < 2; mf++) {
            #pragma unroll
            for (int nf = 0; nf < 8; nf++) {
                const int n = n0 + nf * 8 + q4 * 2;
                const int mA = m0 + mf * 16 + gid;
                float2 v0 = { acc[mf][nf][0] * scale, acc[mf][nf][1] * scale };
                float2 v1 = { acc[mf][nf][2] * scale, acc[mf][nf][3] * scale };
                *(float2*)(Cb + (size_t)mA * ldo + n)       = v0;
                *(float2*)(Cb + (size_t)(mA + 8) * ldo + n) = v1;
            }
        }
    } else if (EPI == EPI_PACKA || EPI == EPI_PACKB) {
        __nv_bfloat16* Ob = (__nv_bfloat16*)Cv;
        #pragma unroll
        for (int mf = 0; mf < 2; mf++) {
            #pragma unroll
            for (int nf = 0; nf < 8; nf++) {
                const int n = n0 + nf * 8 + q4 * 2;
                const float bx = __ldg(bias + n), by = __ldg(bias + n + 1);
                #pragma unroll
                for (int h = 0; h < 2; h++) {
                    const int mA = m0 + mf * 16 + gid + h * 8;
                    float vx = acc[mf][nf][2*h]   + bx;
                    float vy = acc[mf][nf][2*h+1] + by;
                    __nv_bfloat16 hx, lx, hy, ly;
                    split2(vx, hx, lx); split2(vy, hy, ly);
                    __nv_bfloat16* base = Ob + (size_t)mA * ldo + n;
                    *(__nv_bfloat162*)(base) = {hx, hy};
                    if (EPI == EPI_PACKA) {
                        *(__nv_bfloat162*)(base + seg)     = {lx, ly};
                        *(__nv_bfloat162*)(base + 2*seg)   = {hx, hy};
                    } else {
                        *(__nv_bfloat162*)(base + seg)     = {hx, hy};
                        *(__nv_bfloat162*)(base + 2*seg)   = {lx, ly};
                    }
                }
            }
        }
    } else { // EPI_VT : v-projection, transposed pack [b, OD, KPS]=[hi|hi|lo]
        cp_wait<0>();
        __syncthreads();
        // per-warp 32x64 fp32 staging tile (padded to 65 cols)
        float* st = (float*)(dsm + (STG - raw)) + wid * (32 * 65);
        #pragma unroll
        for (int mf = 0; mf < 2; mf++) {
            #pragma unroll
            for (int nf = 0; nf < 8; nf++) {
                const int c = nf * 8 + q4 * 2;
                const int n = n0 + c;
                const float bx = __ldg(bias + n), by = __ldg(bias + n + 1);
                st[(mf*16 + gid)     * 65 + c]     = acc[mf][nf][0] + bx;
                st[(mf*16 + gid)     * 65 + c + 1] = acc[mf][nf][1] + by;
                st[(mf*16 + gid + 8) * 65 + c]     = acc[mf][nf][2] + bx;
                st[(mf*16 + gid + 8) * 65 + c + 1] = acc[mf][nf][3] + by;
            }
        }
        __syncwarp();
        __nv_bfloat16* vt = (__nv_bfloat16*)Cv;
        const int bidx = m0 >> 11;        // batch
        const int s    = m0 & 2047;       // seq offset (m0 multiple of 32)
        #pragma unroll
        for (int cc = 0; cc < 2; cc++) {
            const int c = lane + cc * 32;
            const int o = n0 + c;
            __nv_bfloat16 hi[32], lo[32];
            #pragma unroll
            for (int r = 0; r < 32; r++) split2(st[r * 65 + c], hi[r], lo[r]);
            __nv_bfloat16* dst = vt + ((size_t)bidx * OD + o) * KPS + s;
            #pragma unroll
            for (int r = 0; r < 32; r += 2) {
                *(__nv_bfloat162*)(dst + r)        = {hi[r], hi[r+1]};
                *(__nv_bfloat162*)(dst + 2048 + r) = {hi[r], hi[r+1]};
                *(__nv_bfloat162*)(dst + 4096 + r) = {lo[r], lo[r+1]};
            }
        }
    }
}

// ---------------------------------------------------------------------------
// split-pack: in [R,D] fp32 -> out [R,3D] bf16.  APACK: [hi|lo|hi], else [hi|hi|lo]
// ---------------------------------------------------------------------------
template<bool APACK>
__global__ __launch_bounds__(256)
void pack_split(const float* __restrict__ in, __nv_bfloat16* __restrict__ out,
                int D, size_t total4)
{
    size_t i = (size_t)blockIdx.x * 256 + threadIdx.x;
    if (i >= total4) return;
    const int d4 = D >> 2;
    size_t r = i / d4;
    int c = (int)(i % d4) * 4;
    float4 x = *(const float4*)(in + r * D + c);
    __nv_bfloat16 h[4], l[4];
    split2(x.x, h[0], l[0]); split2(x.y, h[1], l[1]);
    split2(x.z, h[2], l[2]); split2(x.w, h[3], l[3]);
    __nv_bfloat16* o = out + r * (size_t)(3 * D) + c;
    *(__nv_bfloat162*)(o + 0) = {h[0], h[1]};
    *(__nv_bfloat162*)(o + 2) = {h[2], h[3]};
    __nv_bfloat16* o1 = o + D, * o2 = o + 2 * D;
    if (APACK) {
        *(__nv_bfloat162*)(o1 + 0) = {l[0], l[1]}; *(__nv_bfloat162*)(o1 + 2) = {l[2], l[3]};
        *(__nv_bfloat162*)(o2 + 0) = {h[0], h[1]}; *(__nv_bfloat162*)(o2 + 2) = {h[2], h[3]};
    } else {
        *(__nv_bfloat162*)(o1 + 0) = {h[0], h[1]}; *(__nv_bfloat162*)(o1 + 2) = {h[2], h[3]};
        *(__nv_bfloat162*)(o2 + 0) = {l[0], l[1]}; *(__nv_bfloat162*)(o2 + 2) = {l[2], l[3]};
    }
}

// ---------------------------------------------------------------------------
// softmax over rows (len 2048) -> packed probs [hi|lo|hi] rows of 6144
// ---------------------------------------------------------------------------
__global__ __launch_bounds__(256)
void softmax_pack(const float* __restrict__ S, __nv_bfloat16* __restrict__ P)
{
    const float* row = S + (size_t)blockIdx.x * LSEQ;
    __nv_bfloat16* prow = P + (size_t)blockIdx.x * KPS;
    const int tid = threadIdx.x, lane = tid & 31, warp = tid >> 5;
    const int b0 = tid * 8;
    float4 x0 = *(const float4*)(row + b0);
    float4 x1 = *(const float4*)(row + b0 + 4);
    float v[8] = {x0.x, x0.y, x0.z, x0.w, x1.x, x1.y, x1.z, x1.w};
    __shared__ float red[8];
    float mx = v[0];
    #pragma unroll
    for (int i = 1; i < 8; i++) mx = fmaxf(mx, v[i]);
    #pragma unroll
    for (int o = 16; o > 0; o >>= 1) mx = fmaxf(mx, __shfl_xor_sync(~0u, mx, o));
    if (lane == 0) red[warp] = mx;
    __syncthreads();
    float m = red[0];
    #pragma unroll
    for (int i = 1; i < 8; i++) m = fmaxf(m, red[i]);
    __syncthreads();
    float s = 0.f;
    #pragma unroll
    for (int i = 0; i < 8; i++) { v[i] = __expf(v[i] - m); s += v[i]; }
    #pragma unroll
    for (int o = 16; o > 0; o >>= 1) s += __shfl_xor_sync(~0u, s, o);
    if (lane == 0) red[warp] = s;
    __syncthreads();
    float tot = 0.f;
    #pragma unroll
    for (int i = 0; i < 8; i++) tot += red[i];
    float inv = 1.0f / tot;
    #pragma unroll
    for (int i = 0; i < 8; i += 2) {
        __nv_bfloat16 h0, l0, h1, l1;
        split2(v[i] * inv, h0, l0);
        split2(v[i + 1] * inv, h1, l1);
        *(__nv_bfloat162*)(prow + b0 + i)            = {h0, h1};
        *(__nv_bfloat162*)(prow + LSEQ + b0 + i)     = {l0, l1};
        *(__nv_bfloat162*)(prow + 2 * LSEQ + b0 + i) = {h0, h1};
    }
}

// ---------------------------------------------------------------------------
extern "C" void kernel_launch(void* const* d_in, const int* in_sizes, int n_in,
                              void* d_out, int out_size)
{
    const float* query = (const float*)d_in[0];
    const float* key   = (const float*)d_in[1];
    const float* value = (const float*)d_in[2];
    const float* Wq    = (const float*)d_in[3];
    const float* bq    = (const float*)d_in[4];
    const float* Wk    = (const float*)d_in[5];
    const float* bk    = (const float*)d_in[6];
    const float* Wv    = (const float*)d_in[7];
    const float* bv    = (const float*)d_in[8];
    float*       out   = (float*)d_out;

    __nv_bfloat16 *aq, *ak, *av, *bqp, *bkp, *bvp, *qA, *kB, *vT, *pP;
    float *s;
    cudaGetSymbolAddress((void**)&aq,  g_Aq);
    cudaGetSymbolAddress((void**)&ak,  g_Ak);
    cudaGetSymbolAddress((void**)&av,  g_Av);
    cudaGetSymbolAddress((void**)&bqp, g_Bq);
    cudaGetSymbolAddress((void**)&bkp, g_Bk);
    cudaGetSymbolAddress((void**)&bvp, g_Bv);
    cudaGetSymbolAddress((void**)&qA,  g_qA);
    cudaGetSymbolAddress((void**)&kB,  g_kB);
    cudaGetSymbolAddress((void**)&vT,  g_vT);
    cudaGetSymbolAddress((void**)&s,   g_s);
    cudaGetSymbolAddress((void**)&pP,  g_p);

    cudaFuncSetAttribute(mma_gemm<EPI_F32>,   cudaFuncAttributeMaxDynamicSharedMemorySize, GSMEM);
    cudaFuncSetAttribute(mma_gemm<EPI_PACKA>, cudaFuncAttributeMaxDynamicSharedMemorySize, GSMEM);
    cudaFuncSetAttribute(mma_gemm<EPI_PACKB>, cudaFuncAttributeMaxDynamicSharedMemorySize, GSMEM);
    cudaFuncSetAttribute(mma_gemm<EPI_VT>,    cudaFuncAttributeMaxDynamicSharedMemorySize, GSMEM);

    const int M = NB * LSEQ;  // 32768

    // 1) split-pack inputs and weights (GEMM operand layouts)
    pack_split<true ><<<(M * QD / 4 + 255) / 256, 256>>>(query, aq, QD, (size_t)M * QD / 4);
    pack_split<true ><<<(M * KD / 4 + 255) / 256, 256>>>(key,   ak, KD, (size_t)M * KD / 4);
    pack_split<true ><<<(M * KD / 4 + 255) / 256, 256>>>(value, av, KD, (size_t)M * KD / 4);
    pack_split<false><<<(OD * QD / 4 + 255) / 256, 256>>>(Wq, bqp, QD, (size_t)OD * QD / 4);
    pack_split<false><<<(OD * KD / 4 + 255) / 256, 256>>>(Wk, bkp, KD, (size_t)OD * KD / 4);
    pack_split<false><<<(OD * KD / 4 + 255) / 256, 256>>>(Wv, bvp, KD, (size_t)OD * KD / 4);

    // 2) projections with fused pack epilogues
    mma_gemm<EPI_PACKA><<<dim3(OD/128, M/128, 1), 256, GSMEM>>>(
        aq, bqp, qA, bq, KPQ, 0, 0, 0, 3*OD, OD, 1.f);
    mma_gemm<EPI_PACKB><<<dim3(OD/128, M/128, 1), 256, GSMEM>>>(
        ak, bkp, kB, bk, KPK, 0, 0, 0, 3*OD, OD, 1.f);
    mma_gemm<EPI_VT><<<dim3(OD/128, M/128, 1), 256, GSMEM>>>(
        av, bvp, vT, bv, KPK, 0, 0, 0, 0, 0, 1.f);

    // 3) scores = (q k^T)/32, per batch
    mma_gemm<EPI_F32><<<dim3(LSEQ/128, LSEQ/128, NB), 256, GSMEM>>>(
        qA, kB, s, nullptr, 3*OD,
        (size_t)LSEQ*3*OD, (size_t)LSEQ*3*OD, (size_t)LSEQ*LSEQ, LSEQ, 0, 0.03125f);

    // 4) softmax + pack probs
    softmax_pack<<<NB * LSEQ, 256>>>(s, pP);

    // 5) out = probs @ v, per batch
    mma_gemm<EPI_F32><<<dim3(OD/128, LSEQ/128, NB), 256, GSMEM>>>(
        pP, vT, out, nullptr, KPS,
        (size_t)LSEQ*KPS, (size_t)OD*KPS, (size_t)LSEQ*OD, OD, 0, 1.f);
}